// round 3
// baseline (speedup 1.0000x reference)
#include <cuda_runtime.h>
#include <cuda_bf16.h>
#include <cstdint>

// Inverse 2x2 Haar synthesis, output-centric, 256-bit stores (sm_100a+).
// Input  x: [B=8, 4*C=256, H=256, W=256] fp32  (subband-major: k*C + c)
// Output o: [B=8, C=64, 2H=512, 2W=512] fp32
//
// Each thread: 4 x LDG.128 (one float4 per subband, cols 4j..4j+3)
//              2 x STG.256 (8 output cols per row, rows 2h and 2h+1)
// All accesses fully coalesced; stores are 32B-aligned per lane.

static constexpr int B   = 8;
static constexpr int C   = 64;
static constexpr int H   = 256;
static constexpr int W   = 256;
static constexpr int W4  = W / 4;          // 64 float4 per input row
static constexpr int OW  = 2 * W;          // 512 floats per output row

// float4 strides (input)
static constexpr int IN_CH_STRIDE4 = H * W4;                 // 16384
static constexpr int IN_K_STRIDE4  = C * IN_CH_STRIDE4;      // 1,048,576
static constexpr int IN_B_STRIDE4  = 4 * IN_K_STRIDE4;

static constexpr unsigned N_THREADS_TOTAL = (unsigned)B * C * H * W4;  // 8,388,608

__device__ __forceinline__ float4 ldcs4(const float4* p) {
    float4 v;
    asm volatile("ld.global.cs.v4.f32 {%0, %1, %2, %3}, [%4];"
                 : "=f"(v.x), "=f"(v.y), "=f"(v.z), "=f"(v.w) : "l"(p));
    return v;
}

__device__ __forceinline__ void stcs8(float* p,
                                      float a0, float a1, float a2, float a3,
                                      float a4, float a5, float a6, float a7) {
    asm volatile("st.global.cs.v8.f32 [%0], {%1, %2, %3, %4, %5, %6, %7, %8};"
                 :: "l"(p),
                    "f"(a0), "f"(a1), "f"(a2), "f"(a3),
                    "f"(a4), "f"(a5), "f"(a6), "f"(a7));
}

__global__ __launch_bounds__(256)
void iwt_kernel(const float4* __restrict__ in, float* __restrict__ out)
{
    unsigned i = blockIdx.x * blockDim.x + threadIdx.x;   // < 2^23
    // decompose: i = ((b*C + c)*H + h)*W4 + j
    unsigned j  = i & (W4 - 1);
    unsigned t  = i >> 6;
    unsigned h  = t & (H - 1);
    unsigned t2 = t >> 8;
    unsigned c  = t2 & (C - 1);
    unsigned b  = t2 >> 6;

    unsigned in_base = b * IN_B_STRIDE4 + c * IN_CH_STRIDE4 + h * W4 + j;

    float4 ll = ldcs4(in + in_base + 0 * IN_K_STRIDE4);
    float4 lh = ldcs4(in + in_base + 1 * IN_K_STRIDE4);
    float4 hl = ldcs4(in + in_base + 2 * IN_K_STRIDE4);
    float4 hh = ldcs4(in + in_base + 3 * IN_K_STRIDE4);

    // butterflies per input column
    float s1x = ll.x + lh.x, s2x = hl.x + hh.x, d1x = ll.x - lh.x, d2x = hl.x - hh.x;
    float s1y = ll.y + lh.y, s2y = hl.y + hh.y, d1y = ll.y - lh.y, d2y = hl.y - hh.y;
    float s1z = ll.z + lh.z, s2z = hl.z + hh.z, d1z = ll.z - lh.z, d2z = hl.z - hh.z;
    float s1w = ll.w + lh.w, s2w = hl.w + hh.w, d1w = ll.w - lh.w, d2w = hl.w - hh.w;

    const float q = 0.25f;

    // output float index: ((b*C + c)*512 + 2h)*512 + 8j
    unsigned out_base = ((b * C + c) * (2 * H) + 2 * h) * OW + 8 * j;

    // row 2h: interleave (o00, o01) per input column
    stcs8(out + out_base,
          (s1x + s2x) * q, (s1x - s2x) * q,
          (s1y + s2y) * q, (s1y - s2y) * q,
          (s1z + s2z) * q, (s1z - s2z) * q,
          (s1w + s2w) * q, (s1w - s2w) * q);

    // row 2h+1: interleave (o10, o11)
    stcs8(out + out_base + OW,
          (d1x + d2x) * q, (d1x - d2x) * q,
          (d1y + d2y) * q, (d1y - d2y) * q,
          (d1z + d2z) * q, (d1z - d2z) * q,
          (d1w + d2w) * q, (d1w - d2w) * q);
}

extern "C" void kernel_launch(void* const* d_in, const int* in_sizes, int n_in,
                              void* d_out, int out_size)
{
    const float4* in  = (const float4*)d_in[0];
    float*        out = (float*)d_out;

    const int threads = 256;
    const int blocks  = (int)(N_THREADS_TOTAL / threads);   // 32768

    iwt_kernel<<<blocks, threads>>>(in, out);
}

// round 4
// speedup vs baseline: 1.0004x; 1.0004x over previous
#include <cuda_runtime.h>
#include <cuda_bf16.h>
#include <cstdint>

// Inverse 2x2 Haar synthesis, output-centric, 2 work items per thread
// (batched loads for 2x MLP).
// Input  x: [B=8, 4*C=256, H=256, W=256] fp32  (subband-major: k*C + c)
// Output o: [B=8, C=64, 2H=512, 2W=512] fp32
//
// Work item = one output float4 column position for one output row-pair:
//   loads  4 x LDG.64  (float2 per subband), fully coalesced
//   stores 2 x STG.128 (float4 per row),     fully coalesced
// Each thread does items i and i + N/2; all 8 loads issued up front.

static constexpr int B   = 8;
static constexpr int C   = 64;
static constexpr int H   = 256;
static constexpr int W   = 256;
static constexpr int W2  = W / 2;          // 128 float2 per input row
static constexpr int OW4 = (2 * W) / 4;    // 128 float4 per output row

static constexpr int IN_CH_STRIDE2 = H * W2;                 // 32768
static constexpr int IN_K_STRIDE2  = C * IN_CH_STRIDE2;      // 2,097,152
static constexpr int IN_B_STRIDE2  = 4 * IN_K_STRIDE2;

static constexpr int OUT_CH_STRIDE4 = 2 * H * OW4;           // 65536
static constexpr int OUT_B_STRIDE4  = C * OUT_CH_STRIDE4;

static constexpr unsigned N_ITEMS = (unsigned)B * C * H * OW4;  // 16,777,216
static constexpr unsigned N_HALF  = N_ITEMS / 2;                // 8,388,608

__device__ __forceinline__ float2 ldcs2(const float2* p) {
    float2 v;
    asm volatile("ld.global.cs.v2.f32 {%0, %1}, [%2];"
                 : "=f"(v.x), "=f"(v.y) : "l"(p));
    return v;
}

__device__ __forceinline__ void stcs4(float4* p, float4 v) {
    asm volatile("st.global.cs.v4.f32 [%0], {%1, %2, %3, %4};"
                 :: "l"(p), "f"(v.x), "f"(v.y), "f"(v.z), "f"(v.w));
}

struct Addr { unsigned in_base, out_base; };

__device__ __forceinline__ Addr decode(unsigned i)
{
    // i = ((b*C + c)*H + h)*OW4 + j
    unsigned j  = i & (OW4 - 1);
    unsigned t  = i >> 7;
    unsigned h  = t & (H - 1);
    unsigned t2 = t >> 8;
    unsigned c  = t2 & (C - 1);
    unsigned b  = t2 >> 6;
    Addr a;
    a.in_base  = b * IN_B_STRIDE2 + c * IN_CH_STRIDE2 + h * W2 + j;
    a.out_base = b * OUT_B_STRIDE4 + c * OUT_CH_STRIDE4 + (2 * h) * OW4 + j;
    return a;
}

__global__ __launch_bounds__(512)
void iwt_kernel(const float2* __restrict__ in, float4* __restrict__ out)
{
    unsigned i = blockIdx.x * blockDim.x + threadIdx.x;   // < 2^23

    Addr a0 = decode(i);
    Addr a1 = decode(i + N_HALF);

    // Batch all 8 loads before any dependent use (MLP = 8).
    float2 ll0 = ldcs2(in + a0.in_base + 0 * IN_K_STRIDE2);
    float2 lh0 = ldcs2(in + a0.in_base + 1 * IN_K_STRIDE2);
    float2 hl0 = ldcs2(in + a0.in_base + 2 * IN_K_STRIDE2);
    float2 hh0 = ldcs2(in + a0.in_base + 3 * IN_K_STRIDE2);
    float2 ll1 = ldcs2(in + a1.in_base + 0 * IN_K_STRIDE2);
    float2 lh1 = ldcs2(in + a1.in_base + 1 * IN_K_STRIDE2);
    float2 hl1 = ldcs2(in + a1.in_base + 2 * IN_K_STRIDE2);
    float2 hh1 = ldcs2(in + a1.in_base + 3 * IN_K_STRIDE2);

    const float q = 0.25f;

    // ---- item 0 ----
    {
        float s1x = ll0.x + lh0.x, s2x = hl0.x + hh0.x;
        float d1x = ll0.x - lh0.x, d2x = hl0.x - hh0.x;
        float s1y = ll0.y + lh0.y, s2y = hl0.y + hh0.y;
        float d1y = ll0.y - lh0.y, d2y = hl0.y - hh0.y;

        float4 r0 = make_float4((s1x + s2x) * q, (s1x - s2x) * q,
                                (s1y + s2y) * q, (s1y - s2y) * q);
        float4 r1 = make_float4((d1x + d2x) * q, (d1x - d2x) * q,
                                (d1y + d2y) * q, (d1y - d2y) * q);

        stcs4(out + a0.out_base,       r0);
        stcs4(out + a0.out_base + OW4, r1);
    }

    // ---- item 1 ----
    {
        float s1x = ll1.x + lh1.x, s2x = hl1.x + hh1.x;
        float d1x = ll1.x - lh1.x, d2x = hl1.x - hh1.x;
        float s1y = ll1.y + lh1.y, s2y = hl1.y + hh1.y;
        float d1y = ll1.y - lh1.y, d2y = hl1.y - hh1.y;

        float4 r0 = make_float4((s1x + s2x) * q, (s1x - s2x) * q,
                                (s1y + s2y) * q, (s1y - s2y) * q);
        float4 r1 = make_float4((d1x + d2x) * q, (d1x - d2x) * q,
                                (d1y + d2y) * q, (d1y - d2y) * q);

        stcs4(out + a1.out_base,       r0);
        stcs4(out + a1.out_base + OW4, r1);
    }
}

extern "C" void kernel_launch(void* const* d_in, const int* in_sizes, int n_in,
                              void* d_out, int out_size)
{
    const float2* in  = (const float2*)d_in[0];
    float4*       out = (float4*)d_out;

    const int threads = 512;
    const int blocks  = (int)(N_HALF / threads);   // 16384

    iwt_kernel<<<blocks, threads>>>(in, out);
}